// round 3
// baseline (speedup 1.0000x reference)
#include <cuda_runtime.h>

// ---------------- problem dims ----------------
#define BB   4
#define SS   1024
#define HH   2048
#define NHQ  32
#define NKV  4
#define DH   128
#define NE   32
#define TOPK 8
#define II   768
#define ISD  4096
#define TT   4096          // B*S tokens
#define GQA  8             // NHQ/NKV

// ---------------- scratch (static __device__, no allocs) ----------------
static __device__ float g_x    [(size_t)TT*HH];          // ln1 out
static __device__ float g_q    [(size_t)TT*NHQ*DH];
static __device__ float g_kbuf [(size_t)TT*NKV*DH];
static __device__ float g_vbuf [(size_t)TT*NKV*DH];
static __device__ float g_sc   [(size_t)BB*NHQ*SS*SS];   // 512 MB scores/probs
static __device__ float g_o    [(size_t)TT*NHQ*DH];
static __device__ float g_h    [(size_t)TT*HH];          // residual after attn
static __device__ float g_x2   [(size_t)TT*HH];          // ln2 out
static __device__ float g_act  [(size_t)TT*TOPK*II];     // moe gate*up
static __device__ float g_ys   [(size_t)TT*TOPK*HH];     // per-slot expert out
static __device__ float g_acts [(size_t)TT*ISD];         // shared gate*up
static __device__ float g_shr  [(size_t)TT*HH];          // shared expert out
static __device__ float g_sig  [TT];
static __device__ int   g_cnt  [NE];
static __device__ int   g_cntT [1];
static __device__ int   g_ptok [(size_t)NE*TT];
static __device__ int   g_ppid [(size_t)NE*TT];
static __device__ float g_pw   [(size_t)NE*TT];
static __device__ int   g_idl  [TT];

// ---------------- helpers ----------------
__device__ __forceinline__ float blockReduceSum(float v) {
    __shared__ float sh[32];
    int lane = threadIdx.x & 31, wid = threadIdx.x >> 5;
#pragma unroll
    for (int o = 16; o > 0; o >>= 1) v += __shfl_xor_sync(0xffffffffu, v, o);
    if (lane == 0) sh[wid] = v;
    __syncthreads();
    int nw = blockDim.x >> 5;
    v = (threadIdx.x < nw) ? sh[threadIdx.x] : 0.f;
    if (wid == 0) {
#pragma unroll
        for (int o = 16; o > 0; o >>= 1) v += __shfl_xor_sync(0xffffffffu, v, o);
        if (lane == 0) sh[0] = v;
    }
    __syncthreads();
    v = sh[0];
    __syncthreads();
    return v;
}

__device__ __forceinline__ float blockReduceMax(float v) {
    __shared__ float sh[32];
    int lane = threadIdx.x & 31, wid = threadIdx.x >> 5;
#pragma unroll
    for (int o = 16; o > 0; o >>= 1) v = fmaxf(v, __shfl_xor_sync(0xffffffffu, v, o));
    if (lane == 0) sh[wid] = v;
    __syncthreads();
    int nw = blockDim.x >> 5;
    v = (threadIdx.x < nw) ? sh[threadIdx.x] : -3.0e38f;
    if (wid == 0) {
#pragma unroll
        for (int o = 16; o > 0; o >>= 1) v = fmaxf(v, __shfl_xor_sync(0xffffffffu, v, o));
        if (lane == 0) sh[0] = v;
    }
    __syncthreads();
    v = sh[0];
    __syncthreads();
    return v;
}

// ---------------- elementwise / norm kernels ----------------
__global__ void rmsnorm_k(const float* __restrict__ in, const float* __restrict__ w,
                          float* __restrict__ out, int ncols) {
    long long row = blockIdx.x;
    const float* x = in + row * (long long)ncols;
    float* o = out + row * (long long)ncols;
    float s = 0.f;
    for (int i = threadIdx.x; i < ncols; i += blockDim.x) { float v = x[i]; s += v * v; }
    s = blockReduceSum(s);
    float r = rsqrtf(s / (float)ncols + 1e-6f);
    for (int i = threadIdx.x; i < ncols; i += blockDim.x) o[i] = x[i] * r * w[i];
}

// per-(token,head) rmsnorm over D=128, then NeoX RoPE. blockDim=128
__global__ void qknorm_rope_k(float* __restrict__ qk, const float* __restrict__ w, int nheads) {
    int idx = blockIdx.x;            // t*nheads + h
    int t = idx / nheads;
    int pos = t & (SS - 1);          // s within batch
    float* x = qk + (size_t)idx * DH;
    int d = threadIdx.x;
    float v = x[d];
    float ss = v * v;
#pragma unroll
    for (int o = 16; o > 0; o >>= 1) ss += __shfl_xor_sync(0xffffffffu, ss, o);
    __shared__ float wsum[4];
    if ((d & 31) == 0) wsum[d >> 5] = ss;
    __syncthreads();
    float tot = wsum[0] + wsum[1] + wsum[2] + wsum[3];
    float r = rsqrtf(tot * (1.0f / DH) + 1e-6f);
    float xn = v * r * w[d];
    __shared__ float xs[DH];
    xs[d] = xn;
    __syncthreads();
    int fi = d & 63;
    // inv_freq = theta^{-2fi/D} = exp(-fi * ln(1e6)/64)
    float ang = (float)pos * expf(-0.215867352778f * (float)fi);
    float c = cosf(ang), s = sinf(ang);
    float rot = (d < 64) ? -xs[d + 64] : xs[d - 64];
    x[d] = xn * c + rot * s;
}

// causal softmax over one score row; zeroes j>i. blockDim=256
__global__ void softmax_k(float* __restrict__ sc) {
    long long row = blockIdx.x;          // z*S + i
    int i = (int)(row & (SS - 1));
    float* p = sc + row * (long long)SS;
    int len = i + 1;
    float mx = -3.0e38f;
    for (int j = threadIdx.x; j < len; j += 256) mx = fmaxf(mx, p[j]);
    mx = blockReduceMax(mx);
    float s = 0.f;
    for (int j = threadIdx.x; j < len; j += 256) { float e = expf(p[j] - mx); p[j] = e; s += e; }
    s = blockReduceSum(s);
    float inv = 1.f / s;
    for (int j = threadIdx.x; j < len; j += 256) p[j] *= inv;
    for (int j = len + threadIdx.x; j < SS; j += 256) p[j] = 0.f;
}

__global__ void init_k(int* __restrict__ idl, int* __restrict__ cntT) {
    int i = blockIdx.x * blockDim.x + threadIdx.x;
    if (i < TT) idl[i] = i;
    if (i == 0) cntT[0] = TT;
}

// router: logits = x2 @ Wr, softmax, top-8, normalize, append to expert lists. blockDim=128
__global__ void router_k(const float* __restrict__ X, const float* __restrict__ Wr,
                         int* __restrict__ cnt, int* __restrict__ gtok,
                         int* __restrict__ gpid, float* __restrict__ gpw) {
    int t = blockIdx.x;
    const float* x = X + (size_t)t * HH;
    float part[NE];
#pragma unroll
    for (int e = 0; e < NE; e++) part[e] = 0.f;
    for (int k = threadIdx.x; k < HH; k += 128) {
        float xv = x[k];
        const float* wr = Wr + (size_t)k * NE;
#pragma unroll
        for (int e = 0; e < NE; e++) part[e] += xv * wr[e];
    }
    __shared__ float sh[NE * 128];
#pragma unroll
    for (int e = 0; e < NE; e++) sh[e * 128 + threadIdx.x] = part[e];
    __syncthreads();
    __shared__ float logits[NE];
    if (threadIdx.x < NE) {
        float s = 0.f;
        for (int i = 0; i < 128; i++) s += sh[threadIdx.x * 128 + i];
        logits[threadIdx.x] = s;
    }
    __syncthreads();
    if (threadIdx.x == 0) {
        float mx = -3.0e38f;
        for (int e = 0; e < NE; e++) mx = fmaxf(mx, logits[e]);
        float p[NE], se = 0.f;
        for (int e = 0; e < NE; e++) { p[e] = expf(logits[e] - mx); se += p[e]; }
        float inv = 1.f / se;
        for (int e = 0; e < NE; e++) p[e] *= inv;
        int idx[TOPK]; float val[TOPK]; float vs = 0.f;
        bool used[NE];
        for (int e = 0; e < NE; e++) used[e] = false;
        for (int s = 0; s < TOPK; s++) {
            float bv = -1.f; int bi = 0;
            for (int e = 0; e < NE; e++)
                if (!used[e] && p[e] > bv) { bv = p[e]; bi = e; }
            used[bi] = true; idx[s] = bi; val[s] = bv; vs += bv;
        }
        float invs = 1.f / vs;
        for (int s = 0; s < TOPK; s++) {
            int e = idx[s];
            int pos = atomicAdd(&cnt[e], 1);
            gtok[(size_t)e * TT + pos] = t;
            gpid[(size_t)e * TT + pos] = t * TOPK + s;
            gpw [(size_t)e * TT + pos] = val[s] * invs;
        }
    }
}

__global__ void sig_k(const float* __restrict__ X, const float* __restrict__ Wshg,
                      float* __restrict__ sig) {
    int t = blockIdx.x;
    const float* x = X + (size_t)t * HH;
    float s = 0.f;
    for (int i = threadIdx.x; i < HH; i += blockDim.x) s += x[i] * Wshg[i];
    s = blockReduceSum(s);
    if (threadIdx.x == 0) sig[t] = 1.f / (1.f + expf(-s));
}

__global__ void final_k(const float* __restrict__ h, const float* __restrict__ ys,
                        const float* __restrict__ shr, const float* __restrict__ sig,
                        float* __restrict__ out) {
    long long idx = (long long)blockIdx.x * 256 + threadIdx.x;
    if (idx >= (long long)TT * HH) return;
    int t = (int)(idx >> 11);            // /H (2048)
    int n = (int)(idx & (HH - 1));
    float s = h[idx];
    const float* yr = ys + ((long long)t * TOPK) * HH + n;
#pragma unroll
    for (int k = 0; k < TOPK; k++) s += yr[(long long)k * HH];
    s += shr[idx] * sig[t];
    out[idx] = s;
}

// ---------------- generic SGEMM 128x128x8, 256 thr, 8x8 micro ----------------
// flags: 1=unused, 2=causal tile skip (BM==BN), 4=causal K bound
template<bool TRANSB>
__global__ __launch_bounds__(256)
void sgemm_k(const float* __restrict__ A, const float* __restrict__ B,
             float* __restrict__ C, const float* __restrict__ addC,
             int M, int N, int K, int lda, int ldb, int ldc,
             long long sAb, long long sAh,
             long long sBb, long long sBh,
             long long sCb, long long sCh, long long sCz,
             int HB, int bdiv, float alpha, int flags) {
    const int BM = 128, BN = 128, BK = 8, TM = 8, TN = 8;
    int z = blockIdx.z, bb = 0, hh = 0;
    if (HB > 0) { bb = z / HB; hh = z % HB; }
    const float* Ab = A + (long long)bb * sAb + (long long)hh * sAh;
    const float* Bb = B + (long long)bb * sBb +
                      (bdiv > 0 ? (long long)(hh / bdiv) : (long long)hh) * sBh;
    float* Cb = C + (long long)bb * sCb + (long long)hh * sCh + (long long)z * sCz;

    int brow = blockIdx.y, bcol = blockIdx.x;
    if ((flags & 2) && bcol > brow) return;
    int kEnd = (flags & 4) ? min(K, (brow + 1) * BM) : K;

    __shared__ __align__(16) float As[BK * BM];
    __shared__ __align__(16) float Bs[BK * BN];
    int tid = threadIdx.x;
    int tcol = tid & 15, trow = tid >> 4;

    float acc[TM * TN];
#pragma unroll
    for (int i = 0; i < TM * TN; i++) acc[i] = 0.f;

    int aRow = tid >> 3, aCol = tid & 7;
    const float* Aptr = Ab + (long long)(brow * BM) * lda;
    const float* Bptr = TRANSB ? (Bb + (long long)(bcol * BN) * ldb) : (Bb + bcol * BN);
    int bRow = TRANSB ? (tid >> 3) : (tid >> 7);
    int bCol = TRANSB ? (tid & 7) : (tid & 127);

    for (int kk = 0; kk < kEnd; kk += BK) {
#pragma unroll
        for (int i = 0; i < 4; i++) {
            int r = aRow + i * 32;
            As[aCol * BM + r] = Aptr[(long long)r * lda + kk + aCol];
        }
        if (TRANSB) {
#pragma unroll
            for (int i = 0; i < 4; i++) {
                int n = bRow + i * 32;
                Bs[bCol * BN + n] = Bptr[(long long)n * ldb + kk + bCol];
            }
        } else {
#pragma unroll
            for (int i = 0; i < 4; i++) {
                int r = bRow + i * 2;
                Bs[r * BN + bCol] = Bptr[(long long)(kk + r) * ldb + bCol];
            }
        }
        __syncthreads();
#pragma unroll
        for (int k = 0; k < BK; k++) {
            float4 a0 = *(const float4*)&As[k * BM + trow * TM];
            float4 a1 = *(const float4*)&As[k * BM + trow * TM + 4];
            float4 b0 = *(const float4*)&Bs[k * BN + tcol * TN];
            float4 b1 = *(const float4*)&Bs[k * BN + tcol * TN + 4];
            float ra[TM] = {a0.x, a0.y, a0.z, a0.w, a1.x, a1.y, a1.z, a1.w};
            float rb[TN] = {b0.x, b0.y, b0.z, b0.w, b1.x, b1.y, b1.z, b1.w};
#pragma unroll
            for (int i = 0; i < TM; i++)
#pragma unroll
                for (int j = 0; j < TN; j++) acc[i * TN + j] += ra[i] * rb[j];
        }
        __syncthreads();
    }
#pragma unroll
    for (int i = 0; i < TM; i++) {
        long long row = (long long)brow * BM + trow * TM + i;
        float* crow = Cb + row * ldc + bcol * BN + tcol * TN;
        float v[TN];
#pragma unroll
        for (int j = 0; j < TN; j++) v[j] = acc[i * TN + j] * alpha;
        if (addC) {
            const float* arow = addC + row * ldc + bcol * BN + tcol * TN;
            float4 c0 = *(const float4*)arow;
            float4 c1 = *(const float4*)(arow + 4);
            v[0] += c0.x; v[1] += c0.y; v[2] += c0.z; v[3] += c0.w;
            v[4] += c1.x; v[5] += c1.y; v[6] += c1.z; v[7] += c1.w;
        }
        *(float4*)crow       = make_float4(v[0], v[1], v[2], v[3]);
        *(float4*)(crow + 4) = make_float4(v[4], v[5], v[6], v[7]);
    }
}

// ---------------- grouped gate/up GEMM with silu fusion (also shared expert) ----------
// BM=128, BN=64, BK=8, TM=8, TN=4, 256 threads
__global__ __launch_bounds__(256)
void gateup_k(const float* __restrict__ X, const int* __restrict__ gtok,
              const float* __restrict__ Wg, const float* __restrict__ Wu,
              float* __restrict__ Out, const int* __restrict__ gpid,
              const int* __restrict__ cnt,
              int N, int K, long long wstride, int ldout, int listld) {
    const int BM = 128, BN = 64, BK = 8, TM = 8, TN = 4;
    int e = blockIdx.z;
    int mc = cnt[e];
    int m0 = blockIdx.y * BM;
    if (m0 >= mc) return;
    int n0 = blockIdx.x * BN;
    const float* Wgb = Wg + (long long)e * wstride;
    const float* Wub = Wu + (long long)e * wstride;
    const int* lt = gtok + (long long)e * listld;
    const int* lp = gpid + (long long)e * listld;

    __shared__ __align__(16) float As[BK * BM];
    __shared__ __align__(16) float Bgs[BK * BN];
    __shared__ __align__(16) float Bus[BK * BN];
    __shared__ int rowTok[BM];
    __shared__ int rowPid[BM];

    int tid = threadIdx.x;
    if (tid < BM) {
        int m = min(m0 + tid, mc - 1);
        rowTok[tid] = lt[m];
        rowPid[tid] = lp[m];
    }
    __syncthreads();

    int tcol = tid & 15, trow = tid >> 4;
    float accG[TM * TN], accU[TM * TN];
#pragma unroll
    for (int i = 0; i < TM * TN; i++) { accG[i] = 0.f; accU[i] = 0.f; }

    int aRow = tid >> 3, aCol = tid & 7;
    int bRow = tid >> 6, bCol = tid & 63;

    for (int kk = 0; kk < K; kk += BK) {
#pragma unroll
        for (int i = 0; i < 4; i++) {
            int r = aRow + i * 32;
            As[aCol * BM + r] = X[(long long)rowTok[r] * K + kk + aCol];
        }
#pragma unroll
        for (int i = 0; i < 2; i++) {
            int r = bRow + i * 4;
            Bgs[r * BN + bCol] = Wgb[(long long)(kk + r) * N + n0 + bCol];
            Bus[r * BN + bCol] = Wub[(long long)(kk + r) * N + n0 + bCol];
        }
        __syncthreads();
#pragma unroll
        for (int k = 0; k < BK; k++) {
            float4 a0 = *(const float4*)&As[k * BM + trow * TM];
            float4 a1 = *(const float4*)&As[k * BM + trow * TM + 4];
            float4 bg = *(const float4*)&Bgs[k * BN + tcol * TN];
            float4 bu = *(const float4*)&Bus[k * BN + tcol * TN];
            float ra[TM] = {a0.x, a0.y, a0.z, a0.w, a1.x, a1.y, a1.z, a1.w};
            float rg[TN] = {bg.x, bg.y, bg.z, bg.w};
            float ru[TN] = {bu.x, bu.y, bu.z, bu.w};
#pragma unroll
            for (int i = 0; i < TM; i++)
#pragma unroll
                for (int j = 0; j < TN; j++) {
                    accG[i * TN + j] += ra[i] * rg[j];
                    accU[i * TN + j] += ra[i] * ru[j];
                }
        }
        __syncthreads();
    }
#pragma unroll
    for (int i = 0; i < TM; i++) {
        int mr = trow * TM + i;
        if (m0 + mr >= mc) continue;
        int pid = rowPid[mr];
        float* orow = Out + (long long)pid * ldout + n0 + tcol * TN;
        float v[TN];
#pragma unroll
        for (int j = 0; j < TN; j++) {
            float g = accG[i * TN + j], u = accU[i * TN + j];
            v[j] = (g / (1.f + expf(-g))) * u;
        }
        *(float4*)orow = make_float4(v[0], v[1], v[2], v[3]);
    }
}

// ---------------- grouped down-proj GEMM (also shared expert) ----------------
// BM=128, BN=128, BK=8, TM=TN=8, 256 threads
__global__ __launch_bounds__(256)
void down_k(const float* __restrict__ Act, const float* __restrict__ Wd,
            float* __restrict__ Out,
            const int* __restrict__ gpid, const float* __restrict__ pw,
            const int* __restrict__ cnt,
            int N, int K, long long wstride, int ldout, int listld) {
    const int BM = 128, BN = 128, BK = 8, TM = 8, TN = 8;
    int e = blockIdx.z;
    int mc = cnt[e];
    int m0 = blockIdx.y * BM;
    if (m0 >= mc) return;
    int n0 = blockIdx.x * BN;
    const float* Wb = Wd + (long long)e * wstride;

    __shared__ __align__(16) float As[BK * BM];
    __shared__ __align__(16) float Bs[BK * BN];
    __shared__ int rowPid[BM];
    __shared__ float rowW[BM];

    int tid = threadIdx.x;
    if (tid < BM) {
        int m = min(m0 + tid, mc - 1);
        rowPid[tid] = gpid[(long long)e * listld + m];
        rowW[tid] = pw ? pw[(long long)e * listld + m] : 1.f;
    }
    __syncthreads();

    int tcol = tid & 15, trow = tid >> 4;
    float acc[TM * TN];
#pragma unroll
    for (int i = 0; i < TM * TN; i++) acc[i] = 0.f;

    int aRow = tid >> 3, aCol = tid & 7;
    int bRow = tid >> 7, bCol = tid & 127;

    for (int kk = 0; kk < K; kk += BK) {
#pragma unroll
        for (int i = 0; i < 4; i++) {
            int r = aRow + i * 32;
            As[aCol * BM + r] = Act[(long long)rowPid[r] * K + kk + aCol];
        }
#pragma unroll
        for (int i = 0; i < 4; i++) {
            int r = bRow + i * 2;
            Bs[r * BN + bCol] = Wb[(long long)(kk + r) * N + n0 + bCol];
        }
        __syncthreads();
#pragma unroll
        for (int k = 0; k < BK; k++) {
            float4 a0 = *(const float4*)&As[k * BM + trow * TM];
            float4 a1 = *(const float4*)&As[k * BM + trow * TM + 4];
            float4 b0 = *(const float4*)&Bs[k * BN + tcol * TN];
            float4 b1 = *(const float4*)&Bs[k * BN + tcol * TN + 4];
            float ra[TM] = {a0.x, a0.y, a0.z, a0.w, a1.x, a1.y, a1.z, a1.w};
            float rb[TN] = {b0.x, b0.y, b0.z, b0.w, b1.x, b1.y, b1.z, b1.w};
#pragma unroll
            for (int i = 0; i < TM; i++)
#pragma unroll
                for (int j = 0; j < TN; j++) acc[i * TN + j] += ra[i] * rb[j];
        }
        __syncthreads();
    }
#pragma unroll
    for (int i = 0; i < TM; i++) {
        int mr = trow * TM + i;
        if (m0 + mr >= mc) continue;
        int pid = rowPid[mr];
        float w = rowW[mr];
        float* orow = Out + (long long)pid * ldout + n0 + tcol * TN;
        *(float4*)orow = make_float4(acc[i*TN+0]*w, acc[i*TN+1]*w, acc[i*TN+2]*w, acc[i*TN+3]*w);
        *(float4*)(orow + 4) = make_float4(acc[i*TN+4]*w, acc[i*TN+5]*w, acc[i*TN+6]*w, acc[i*TN+7]*w);
    }
}

// ---------------- host ----------------
extern "C" void kernel_launch(void* const* d_in, const int* in_sizes, int n_in,
                              void* d_out, int out_size) {
    const float* hidden = (const float*)d_in[0];
    const float* ln1w   = (const float*)d_in[1];
    const float* ln2w   = (const float*)d_in[2];
    const float* qnw    = (const float*)d_in[3];
    const float* knw    = (const float*)d_in[4];
    const float* Wq     = (const float*)d_in[5];
    const float* Wk     = (const float*)d_in[6];
    const float* Wv     = (const float*)d_in[7];
    const float* Wo     = (const float*)d_in[8];
    const float* Wr     = (const float*)d_in[9];
    const float* Weg    = (const float*)d_in[10];
    const float* Weu    = (const float*)d_in[11];
    const float* Wed    = (const float*)d_in[12];
    const float* Wsg    = (const float*)d_in[13];
    const float* Wsu    = (const float*)d_in[14];
    const float* Wsd    = (const float*)d_in[15];
    const float* Wshg   = (const float*)d_in[16];
    float* out = (float*)d_out;

    float *x, *q, *kb, *vb, *sc, *o, *h, *x2, *act, *ys, *acts, *shr, *sig, *pw;
    int *cnt, *cntT, *ptok, *ppid, *idl;
    cudaGetSymbolAddress((void**)&x,    g_x);
    cudaGetSymbolAddress((void**)&q,    g_q);
    cudaGetSymbolAddress((void**)&kb,   g_kbuf);
    cudaGetSymbolAddress((void**)&vb,   g_vbuf);
    cudaGetSymbolAddress((void**)&sc,   g_sc);
    cudaGetSymbolAddress((void**)&o,    g_o);
    cudaGetSymbolAddress((void**)&h,    g_h);
    cudaGetSymbolAddress((void**)&x2,   g_x2);
    cudaGetSymbolAddress((void**)&act,  g_act);
    cudaGetSymbolAddress((void**)&ys,   g_ys);
    cudaGetSymbolAddress((void**)&acts, g_acts);
    cudaGetSymbolAddress((void**)&shr,  g_shr);
    cudaGetSymbolAddress((void**)&sig,  g_sig);
    cudaGetSymbolAddress((void**)&pw,   g_pw);
    cudaGetSymbolAddress((void**)&cnt,  g_cnt);
    cudaGetSymbolAddress((void**)&cntT, g_cntT);
    cudaGetSymbolAddress((void**)&ptok, g_ptok);
    cudaGetSymbolAddress((void**)&ppid, g_ppid);
    cudaGetSymbolAddress((void**)&idl,  g_idl);

    const float scale = 0.08838834764831845f;   // D^-0.5

    // 1) ln1
    rmsnorm_k<<<TT, 256>>>(hidden, ln1w, x, HH);
    // 2) q,k,v projections
    sgemm_k<false><<<dim3(32, 32, 1), 256>>>(x, Wq, q, nullptr, TT, NHQ*DH, HH,
        HH, NHQ*DH, NHQ*DH, 0,0,0,0,0,0,0, 0,0, 1.f, 0);
    sgemm_k<false><<<dim3(4, 32, 1), 256>>>(x, Wk, kb, nullptr, TT, NKV*DH, HH,
        HH, NKV*DH, NKV*DH, 0,0,0,0,0,0,0, 0,0, 1.f, 0);
    sgemm_k<false><<<dim3(4, 32, 1), 256>>>(x, Wv, vb, nullptr, TT, NKV*DH, HH,
        HH, NKV*DH, NKV*DH, 0,0,0,0,0,0,0, 0,0, 1.f, 0);
    // 3) q/k rmsnorm + rope
    qknorm_rope_k<<<TT * NHQ, DH>>>(q, qnw, NHQ);
    qknorm_rope_k<<<TT * NKV, DH>>>(kb, knw, NKV);
    // 4) scores = scale * q @ k^T (causal tile-skip), batched over B*NH
    sgemm_k<true><<<dim3(8, 8, BB * NHQ), 256>>>(q, kb, sc, nullptr, SS, SS, DH,
        NHQ*DH, NKV*DH, SS,
        (long long)SS*NHQ*DH, DH,
        (long long)SS*NKV*DH, DH,
        0, 0, (long long)SS*SS,
        NHQ, GQA, scale, 2);
    // 5) causal softmax
    softmax_k<<<BB * NHQ * SS, 256>>>(sc);
    // 6) o = p @ v (causal K bound)
    sgemm_k<false><<<dim3(1, 8, BB * NHQ), 256>>>(sc, vb, o, nullptr, SS, DH, SS,
        SS, NKV*DH, NHQ*DH,
        (long long)NHQ*SS*SS, (long long)SS*SS,
        (long long)SS*NKV*DH, DH,
        (long long)SS*NHQ*DH, DH, 0,
        NHQ, GQA, 1.f, 4);
    // 7) h = hidden + o @ Wo
    sgemm_k<false><<<dim3(16, 32, 1), 256>>>(o, Wo, h, hidden, TT, HH, NHQ*DH,
        NHQ*DH, HH, HH, 0,0,0,0,0,0,0, 0,0, 1.f, 0);
    // 8) ln2
    rmsnorm_k<<<TT, 256>>>(h, ln2w, x2, HH);
    // 9) routing
    cudaMemsetAsync(cnt, 0, NE * sizeof(int), 0);
    init_k<<<TT / 256, 256>>>(idl, cntT);
    router_k<<<TT, 128>>>(x2, Wr, cnt, ptok, ppid, pw);
    // 10) MoE experts: gate/up (silu fused) then down (weighted, per-slot)
    gateup_k<<<dim3(II / 64, TT / 128, NE), 256>>>(x2, ptok, Weg, Weu, act, ppid, cnt,
        II, HH, (long long)HH * II, II, TT);
    down_k<<<dim3(HH / 128, TT / 128, NE), 256>>>(act, Wed, ys, ppid, pw, cnt,
        HH, II, (long long)II * HH, HH, TT);
    // 11) shared expert via same kernels with identity lists
    gateup_k<<<dim3(ISD / 64, TT / 128, 1), 256>>>(x2, idl, Wsg, Wsu, acts, idl, cntT,
        ISD, HH, 0, ISD, TT);
    down_k<<<dim3(HH / 128, TT / 128, 1), 256>>>(acts, Wsd, shr, idl, nullptr, cntT,
        HH, ISD, 0, HH, TT);
    sig_k<<<TT, 256>>>(x2, Wshg, sig);
    // 12) out = h + sum(slots) + shared*sigmoid
    final_k<<<(TT * HH) / 256, 256>>>(h, ys, shr, sig, out);
}

// round 4
// speedup vs baseline: 2.2679x; 2.2679x over previous
#include <cuda_runtime.h>
#include <cstdint>

// ---------------- problem dims ----------------
#define BB   4
#define SS   1024
#define HH   2048
#define NHQ  32
#define NKV  4
#define DH   128
#define NE   32
#define TOPK 8
#define II   768
#define ISD  4096
#define TT   4096          // B*S tokens
#define GQA  8             // NHQ/NKV

// ---------------- scratch (static __device__, no allocs) ----------------
static __device__ float g_x    [(size_t)TT*HH];          // ln1 out
static __device__ float g_q    [(size_t)TT*NHQ*DH];
static __device__ float g_kbuf [(size_t)TT*NKV*DH];
static __device__ float g_vbuf [(size_t)TT*NKV*DH];
static __device__ float g_sc   [(size_t)BB*NHQ*SS*SS];   // 512 MB scores/probs
static __device__ float g_o    [(size_t)TT*NHQ*DH];
static __device__ float g_h    [(size_t)TT*HH];          // residual after attn
static __device__ float g_x2   [(size_t)TT*HH];          // ln2 out
static __device__ float g_act  [(size_t)TT*TOPK*II];     // moe gate*up
static __device__ float g_ys   [(size_t)TT*TOPK*HH];     // per-slot expert out
static __device__ float g_acts [(size_t)TT*ISD];         // shared gate*up
static __device__ float g_shr  [(size_t)TT*HH];          // shared expert out
static __device__ float g_sig  [TT];
static __device__ int   g_cnt  [NE];
static __device__ int   g_cntT [1];
static __device__ int   g_ptok [(size_t)NE*TT];
static __device__ int   g_ppid [(size_t)NE*TT];
static __device__ float g_pw   [(size_t)NE*TT];
static __device__ int   g_idl  [TT];

// ---------------- helpers ----------------
__device__ __forceinline__ float blockReduceSum(float v) {
    __shared__ float sh[32];
    int lane = threadIdx.x & 31, wid = threadIdx.x >> 5;
#pragma unroll
    for (int o = 16; o > 0; o >>= 1) v += __shfl_xor_sync(0xffffffffu, v, o);
    if (lane == 0) sh[wid] = v;
    __syncthreads();
    int nw = blockDim.x >> 5;
    v = (threadIdx.x < nw) ? sh[threadIdx.x] : 0.f;
    if (wid == 0) {
#pragma unroll
        for (int o = 16; o > 0; o >>= 1) v += __shfl_xor_sync(0xffffffffu, v, o);
        if (lane == 0) sh[0] = v;
    }
    __syncthreads();
    v = sh[0];
    __syncthreads();
    return v;
}

__device__ __forceinline__ float blockReduceMax(float v) {
    __shared__ float sh[32];
    int lane = threadIdx.x & 31, wid = threadIdx.x >> 5;
#pragma unroll
    for (int o = 16; o > 0; o >>= 1) v = fmaxf(v, __shfl_xor_sync(0xffffffffu, v, o));
    if (lane == 0) sh[wid] = v;
    __syncthreads();
    int nw = blockDim.x >> 5;
    v = (threadIdx.x < nw) ? sh[threadIdx.x] : -3.0e38f;
    if (wid == 0) {
#pragma unroll
        for (int o = 16; o > 0; o >>= 1) v = fmaxf(v, __shfl_xor_sync(0xffffffffu, v, o));
        if (lane == 0) sh[0] = v;
    }
    __syncthreads();
    v = sh[0];
    __syncthreads();
    return v;
}

// tf32 helpers
__device__ __forceinline__ float tf32r(float x) {
    uint32_t r;
    asm("cvt.rna.tf32.f32 %0, %1;" : "=r"(r) : "f"(x));
    return __uint_as_float(r);
}
__device__ __forceinline__ void mma_tf32(float* c, const uint32_t* a, const uint32_t* b) {
    asm volatile(
        "mma.sync.aligned.m16n8k8.row.col.f32.tf32.tf32.f32 "
        "{%0,%1,%2,%3}, {%4,%5,%6,%7}, {%8,%9}, {%0,%1,%2,%3};\n"
        : "+f"(c[0]), "+f"(c[1]), "+f"(c[2]), "+f"(c[3])
        : "r"(a[0]), "r"(a[1]), "r"(a[2]), "r"(a[3]), "r"(b[0]), "r"(b[1]));
}

// ---------------- elementwise / norm kernels ----------------
__global__ void rmsnorm_k(const float* __restrict__ in, const float* __restrict__ w,
                          float* __restrict__ out, int ncols) {
    long long row = blockIdx.x;
    const float* x = in + row * (long long)ncols;
    float* o = out + row * (long long)ncols;
    float s = 0.f;
    for (int i = threadIdx.x; i < ncols; i += blockDim.x) { float v = x[i]; s += v * v; }
    s = blockReduceSum(s);
    float r = rsqrtf(s / (float)ncols + 1e-6f);
    for (int i = threadIdx.x; i < ncols; i += blockDim.x) o[i] = x[i] * r * w[i];
}

// per-(token,head) rmsnorm over D=128, then NeoX RoPE. blockDim=128
__global__ void qknorm_rope_k(float* __restrict__ qk, const float* __restrict__ w, int nheads) {
    int idx = blockIdx.x;            // t*nheads + h
    int t = idx / nheads;
    int pos = t & (SS - 1);          // s within batch
    float* x = qk + (size_t)idx * DH;
    int d = threadIdx.x;
    float v = x[d];
    float ss = v * v;
#pragma unroll
    for (int o = 16; o > 0; o >>= 1) ss += __shfl_xor_sync(0xffffffffu, ss, o);
    __shared__ float wsum[4];
    if ((d & 31) == 0) wsum[d >> 5] = ss;
    __syncthreads();
    float tot = wsum[0] + wsum[1] + wsum[2] + wsum[3];
    float r = rsqrtf(tot * (1.0f / DH) + 1e-6f);
    float xn = v * r * w[d];
    __shared__ float xs[DH];
    xs[d] = xn;
    __syncthreads();
    int fi = d & 63;
    float ang = (float)pos * expf(-0.215867352778f * (float)fi);
    float c = cosf(ang), s = sinf(ang);
    float rot = (d < 64) ? -xs[d + 64] : xs[d - 64];
    x[d] = xn * c + rot * s;
}

// causal softmax over one score row; zeroes j>i. blockDim=256
__global__ void softmax_k(float* __restrict__ sc) {
    long long row = blockIdx.x;          // z*S + i
    int i = (int)(row & (SS - 1));
    float* p = sc + row * (long long)SS;
    int len = i + 1;
    float mx = -3.0e38f;
    for (int j = threadIdx.x; j < len; j += 256) mx = fmaxf(mx, p[j]);
    mx = blockReduceMax(mx);
    float s = 0.f;
    for (int j = threadIdx.x; j < len; j += 256) { float e = expf(p[j] - mx); p[j] = e; s += e; }
    s = blockReduceSum(s);
    float inv = 1.f / s;
    for (int j = threadIdx.x; j < len; j += 256) p[j] *= inv;
    for (int j = len + threadIdx.x; j < SS; j += 256) p[j] = 0.f;
}

__global__ void init_k(int* __restrict__ idl, int* __restrict__ cntT) {
    int i = blockIdx.x * blockDim.x + threadIdx.x;
    if (i < TT) idl[i] = i;
    if (i == 0) cntT[0] = TT;
}

// router: logits = x2 @ Wr, softmax, top-8, normalize, append to expert lists. blockDim=128
__global__ void router_k(const float* __restrict__ X, const float* __restrict__ Wr,
                         int* __restrict__ cnt, int* __restrict__ gtok,
                         int* __restrict__ gpid, float* __restrict__ gpw) {
    int t = blockIdx.x;
    const float* x = X + (size_t)t * HH;
    float part[NE];
#pragma unroll
    for (int e = 0; e < NE; e++) part[e] = 0.f;
    for (int k = threadIdx.x; k < HH; k += 128) {
        float xv = x[k];
        const float* wr = Wr + (size_t)k * NE;
#pragma unroll
        for (int e = 0; e < NE; e++) part[e] += xv * wr[e];
    }
    __shared__ float sh[NE * 128];
#pragma unroll
    for (int e = 0; e < NE; e++) sh[e * 128 + threadIdx.x] = part[e];
    __syncthreads();
    __shared__ float logits[NE];
    if (threadIdx.x < NE) {
        float s = 0.f;
        for (int i = 0; i < 128; i++) s += sh[threadIdx.x * 128 + i];
        logits[threadIdx.x] = s;
    }
    __syncthreads();
    if (threadIdx.x == 0) {
        float mx = -3.0e38f;
        for (int e = 0; e < NE; e++) mx = fmaxf(mx, logits[e]);
        float p[NE], se = 0.f;
        for (int e = 0; e < NE; e++) { p[e] = expf(logits[e] - mx); se += p[e]; }
        float inv = 1.f / se;
        for (int e = 0; e < NE; e++) p[e] *= inv;
        int idx[TOPK]; float val[TOPK]; float vs = 0.f;
        bool used[NE];
        for (int e = 0; e < NE; e++) used[e] = false;
        for (int s = 0; s < TOPK; s++) {
            float bv = -1.f; int bi = 0;
            for (int e = 0; e < NE; e++)
                if (!used[e] && p[e] > bv) { bv = p[e]; bi = e; }
            used[bi] = true; idx[s] = bi; val[s] = bv; vs += bv;
        }
        float invs = 1.f / vs;
        for (int s = 0; s < TOPK; s++) {
            int e = idx[s];
            int pos = atomicAdd(&cnt[e], 1);
            gtok[(size_t)e * TT + pos] = t;
            gpid[(size_t)e * TT + pos] = t * TOPK + s;
            gpw [(size_t)e * TT + pos] = val[s] * invs;
        }
    }
}

__global__ void sig_k(const float* __restrict__ X, const float* __restrict__ Wshg,
                      float* __restrict__ sig) {
    int t = blockIdx.x;
    const float* x = X + (size_t)t * HH;
    float s = 0.f;
    for (int i = threadIdx.x; i < HH; i += blockDim.x) s += x[i] * Wshg[i];
    s = blockReduceSum(s);
    if (threadIdx.x == 0) sig[t] = 1.f / (1.f + expf(-s));
}

__global__ void final_k(const float* __restrict__ h, const float* __restrict__ ys,
                        const float* __restrict__ shr, const float* __restrict__ sig,
                        float* __restrict__ out) {
    long long idx = (long long)blockIdx.x * 256 + threadIdx.x;
    if (idx >= (long long)TT * HH) return;
    int t = (int)(idx >> 11);
    int n = (int)(idx & (HH - 1));
    float s = h[idx];
    const float* yr = ys + ((long long)t * TOPK) * HH + n;
#pragma unroll
    for (int k = 0; k < TOPK; k++) s += yr[(long long)k * HH];
    s += shr[idx] * sig[t];
    out[idx] = s;
}

// ---------------- fp32 SGEMM (attention core only) ----------------
// flags: 2=causal tile skip (BM==BN), 4=causal K bound
template<bool TRANSB>
__global__ __launch_bounds__(256)
void sgemm_k(const float* __restrict__ A, const float* __restrict__ B,
             float* __restrict__ C, const float* __restrict__ addC,
             int M, int N, int K, int lda, int ldb, int ldc,
             long long sAb, long long sAh,
             long long sBb, long long sBh,
             long long sCb, long long sCh, long long sCz,
             int HB, int bdiv, float alpha, int flags) {
    const int BM = 128, BN = 128, BK = 8, TM = 8, TN = 8;
    int z = blockIdx.z, bb = 0, hh = 0;
    if (HB > 0) { bb = z / HB; hh = z % HB; }
    const float* Ab = A + (long long)bb * sAb + (long long)hh * sAh;
    const float* Bb = B + (long long)bb * sBb +
                      (bdiv > 0 ? (long long)(hh / bdiv) : (long long)hh) * sBh;
    float* Cb = C + (long long)bb * sCb + (long long)hh * sCh + (long long)z * sCz;

    int brow = blockIdx.y, bcol = blockIdx.x;
    if ((flags & 2) && bcol > brow) return;
    int kEnd = (flags & 4) ? min(K, (brow + 1) * BM) : K;

    __shared__ __align__(16) float As[BK * BM];
    __shared__ __align__(16) float Bs[BK * BN];
    int tid = threadIdx.x;
    int tcol = tid & 15, trow = tid >> 4;

    float acc[TM * TN];
#pragma unroll
    for (int i = 0; i < TM * TN; i++) acc[i] = 0.f;

    int aRow = tid >> 3, aCol = tid & 7;
    const float* Aptr = Ab + (long long)(brow * BM) * lda;
    const float* Bptr = TRANSB ? (Bb + (long long)(bcol * BN) * ldb) : (Bb + bcol * BN);
    int bRow = TRANSB ? (tid >> 3) : (tid >> 7);
    int bCol = TRANSB ? (tid & 7) : (tid & 127);

    for (int kk = 0; kk < kEnd; kk += BK) {
#pragma unroll
        for (int i = 0; i < 4; i++) {
            int r = aRow + i * 32;
            As[aCol * BM + r] = Aptr[(long long)r * lda + kk + aCol];
        }
        if (TRANSB) {
#pragma unroll
            for (int i = 0; i < 4; i++) {
                int n = bRow + i * 32;
                Bs[bCol * BN + n] = Bptr[(long long)n * ldb + kk + bCol];
            }
        } else {
#pragma unroll
            for (int i = 0; i < 4; i++) {
                int r = bRow + i * 2;
                Bs[r * BN + bCol] = Bptr[(long long)(kk + r) * ldb + bCol];
            }
        }
        __syncthreads();
#pragma unroll
        for (int k = 0; k < BK; k++) {
            float4 a0 = *(const float4*)&As[k * BM + trow * TM];
            float4 a1 = *(const float4*)&As[k * BM + trow * TM + 4];
            float4 b0 = *(const float4*)&Bs[k * BN + tcol * TN];
            float4 b1 = *(const float4*)&Bs[k * BN + tcol * TN + 4];
            float ra[TM] = {a0.x, a0.y, a0.z, a0.w, a1.x, a1.y, a1.z, a1.w};
            float rb[TN] = {b0.x, b0.y, b0.z, b0.w, b1.x, b1.y, b1.z, b1.w};
#pragma unroll
            for (int i = 0; i < TM; i++)
#pragma unroll
                for (int j = 0; j < TN; j++) acc[i * TN + j] += ra[i] * rb[j];
        }
        __syncthreads();
    }
#pragma unroll
    for (int i = 0; i < TM; i++) {
        long long row = (long long)brow * BM + trow * TM + i;
        float* crow = Cb + row * ldc + bcol * BN + tcol * TN;
        float v[TN];
#pragma unroll
        for (int j = 0; j < TN; j++) v[j] = acc[i * TN + j] * alpha;
        if (addC) {
            const float* arow = addC + row * ldc + bcol * BN + tcol * TN;
            float4 c0 = *(const float4*)arow;
            float4 c1 = *(const float4*)(arow + 4);
            v[0] += c0.x; v[1] += c0.y; v[2] += c0.z; v[3] += c0.w;
            v[4] += c1.x; v[5] += c1.y; v[6] += c1.z; v[7] += c1.w;
        }
        *(float4*)crow       = make_float4(v[0], v[1], v[2], v[3]);
        *(float4*)(crow + 4) = make_float4(v[4], v[5], v[6], v[7]);
    }
}

// ================= TF32 tensor-core GEMM (single-B) =================
// BM=128, BN=128, BK=16, 256 threads (8 warps: 2 in m x 4 in n), warp tile 64x32.
// Handles: dense (rows=null), grouped gather/scatter (rows=list), per-row weight,
// optional residual addC, per-z expert weight stride.
#define LDAS 20
#define LDBS 132

__global__ __launch_bounds__(256)
void tmm_k(const float* __restrict__ A, const float* __restrict__ Bm,
           float* __restrict__ C, const float* __restrict__ addC,
           const int* __restrict__ rows, const float* __restrict__ wgt,
           const int* __restrict__ cnt, int Mfix,
           int N, int K, int lda, int ldc, long long bstride, int listld) {
    int z = blockIdx.z;
    int mc = cnt ? cnt[z] : Mfix;
    int m0 = blockIdx.y * 128;
    if (m0 >= mc) return;
    int n0 = blockIdx.x * 128;
    const float* Bb = Bm + (long long)z * bstride;
    const int*   rl = rows ? rows + (long long)z * listld : nullptr;
    const float* wl = wgt  ? wgt  + (long long)z * listld : nullptr;

    __shared__ __align__(16) float As[2][128 * LDAS];
    __shared__ __align__(16) float Bs[2][16 * LDBS];
    __shared__ int   rowIdx[128];
    __shared__ float rowW[128];

    int tid = threadIdx.x;
    if (tid < 128) {
        int m = min(m0 + tid, mc - 1);
        rowIdx[tid] = rl ? rl[m] : m;
        rowW[tid]   = wl ? wl[m] : 1.f;
    }
    __syncthreads();

    int warp = tid >> 5, lane = tid & 31;
    int g = lane >> 2, tc = lane & 3;
    int warpM = (warp & 1) * 64, warpN = (warp >> 1) * 32;

    // global load mapping
    int aM = tid & 127, aKq = tid >> 7;                  // A: kq in {aKq, aKq+2}
    int bR = tid >> 5,  bC = tid & 31;                   // B: rows {bR, bR+8}, col bC*4
    const float* aBase = A + (long long)rowIdx[aM] * lda;

    float acc[4][4][4];
#pragma unroll
    for (int i = 0; i < 4; i++)
#pragma unroll
        for (int j = 0; j < 4; j++)
#pragma unroll
            for (int q = 0; q < 4; q++) acc[i][j][q] = 0.f;

    int KT = K / 16;

    // prologue: tile 0
    {
        float4 a0 = *(const float4*)(aBase + aKq * 4);
        float4 a1 = *(const float4*)(aBase + (aKq + 2) * 4);
        const float* bp = Bb + (long long)bR * N + n0 + bC * 4;
        float4 b0 = *(const float4*)bp;
        float4 b1 = *(const float4*)(bp + (long long)8 * N);
        float* as = &As[0][aM * LDAS];
        *(float4*)(as + aKq * 4)       = make_float4(tf32r(a0.x), tf32r(a0.y), tf32r(a0.z), tf32r(a0.w));
        *(float4*)(as + (aKq + 2) * 4) = make_float4(tf32r(a1.x), tf32r(a1.y), tf32r(a1.z), tf32r(a1.w));
        *(float4*)&Bs[0][bR * LDBS + bC * 4]       = make_float4(tf32r(b0.x), tf32r(b0.y), tf32r(b0.z), tf32r(b0.w));
        *(float4*)&Bs[0][(bR + 8) * LDBS + bC * 4] = make_float4(tf32r(b1.x), tf32r(b1.y), tf32r(b1.z), tf32r(b1.w));
    }
    __syncthreads();

    int buf = 0;
    for (int kt = 0; kt < KT; kt++) {
        bool hn = (kt + 1 < KT);
        float4 a0, a1, b0, b1;
        if (hn) {
            int k0 = (kt + 1) * 16;
            a0 = *(const float4*)(aBase + k0 + aKq * 4);
            a1 = *(const float4*)(aBase + k0 + (aKq + 2) * 4);
            const float* bp = Bb + (long long)(k0 + bR) * N + n0 + bC * 4;
            b0 = *(const float4*)bp;
            b1 = *(const float4*)(bp + (long long)8 * N);
        }
        // compute 2 k-steps from smem[buf]
#pragma unroll
        for (int ks = 0; ks < 2; ks++) {
            uint32_t afr[4][4], bfr[4][2];
#pragma unroll
            for (int i = 0; i < 4; i++) {
                const float* ar = &As[buf][(warpM + i * 16 + g) * LDAS + ks * 8 + tc];
                afr[i][0] = __float_as_uint(ar[0]);
                afr[i][1] = __float_as_uint(ar[8 * LDAS]);
                afr[i][2] = __float_as_uint(ar[4]);
                afr[i][3] = __float_as_uint(ar[8 * LDAS + 4]);
            }
#pragma unroll
            for (int j = 0; j < 4; j++) {
                const float* br = &Bs[buf][(ks * 8 + tc) * LDBS + warpN + j * 8 + g];
                bfr[j][0] = __float_as_uint(br[0]);
                bfr[j][1] = __float_as_uint(br[4 * LDBS]);
            }
#pragma unroll
            for (int i = 0; i < 4; i++)
#pragma unroll
                for (int j = 0; j < 4; j++) mma_tf32(acc[i][j], afr[i], bfr[j]);
        }
        if (hn) {
            float* as = &As[buf ^ 1][aM * LDAS];
            *(float4*)(as + aKq * 4)       = make_float4(tf32r(a0.x), tf32r(a0.y), tf32r(a0.z), tf32r(a0.w));
            *(float4*)(as + (aKq + 2) * 4) = make_float4(tf32r(a1.x), tf32r(a1.y), tf32r(a1.z), tf32r(a1.w));
            *(float4*)&Bs[buf ^ 1][bR * LDBS + bC * 4]       = make_float4(tf32r(b0.x), tf32r(b0.y), tf32r(b0.z), tf32r(b0.w));
            *(float4*)&Bs[buf ^ 1][(bR + 8) * LDBS + bC * 4] = make_float4(tf32r(b1.x), tf32r(b1.y), tf32r(b1.z), tf32r(b1.w));
        }
        __syncthreads();
        buf ^= 1;
    }

    // epilogue
#pragma unroll
    for (int i = 0; i < 4; i++) {
#pragma unroll
        for (int half = 0; half < 2; half++) {
            int rr = warpM + i * 16 + g + half * 8;
            if (m0 + rr >= mc) continue;
            int grow = rowIdx[rr];
            float w = rowW[rr];
            float* cp = C + (long long)grow * ldc + n0 + warpN + 2 * tc;
            const float* ap = addC ? addC + (long long)grow * ldc + n0 + warpN + 2 * tc : nullptr;
#pragma unroll
            for (int j = 0; j < 4; j++) {
                float v0 = acc[i][j][half * 2 + 0] * w;
                float v1 = acc[i][j][half * 2 + 1] * w;
                if (ap) {
                    float2 c0 = *(const float2*)(ap + j * 8);
                    v0 += c0.x; v1 += c0.y;
                }
                *(float2*)(cp + j * 8) = make_float2(v0, v1);
            }
        }
    }
}

// ================= TF32 grouped gate/up GEMM with silu fusion =================
// BM=128, BN=64, BK=16, 256 threads (2m x 4n warps), warp tile 64x16.
#define LDBSG 68

__global__ __launch_bounds__(256)
void tgu_k(const float* __restrict__ X,
           const float* __restrict__ Wg, const float* __restrict__ Wu,
           float* __restrict__ Out,
           const int* __restrict__ gtok, const int* __restrict__ gpid,
           const int* __restrict__ cnt, int Mfix,
           int N, int K, long long wstride, int ldout, int listld) {
    int z = blockIdx.z;
    int mc = cnt ? cnt[z] : Mfix;
    int m0 = blockIdx.y * 128;
    if (m0 >= mc) return;
    int n0 = blockIdx.x * 64;
    const float* Wgb = Wg + (long long)z * wstride;
    const float* Wub = Wu + (long long)z * wstride;
    const int* lt = gtok + (long long)z * listld;
    const int* lp = gpid + (long long)z * listld;

    __shared__ __align__(16) float As [2][128 * LDAS];
    __shared__ __align__(16) float Bgs[2][16 * LDBSG];
    __shared__ __align__(16) float Bus[2][16 * LDBSG];
    __shared__ int rowTok[128];
    __shared__ int rowPid[128];

    int tid = threadIdx.x;
    if (tid < 128) {
        int m = min(m0 + tid, mc - 1);
        rowTok[tid] = lt[m];
        rowPid[tid] = lp[m];
    }
    __syncthreads();

    int warp = tid >> 5, lane = tid & 31;
    int g = lane >> 2, tc = lane & 3;
    int warpM = (warp & 1) * 64, warpN = (warp >> 1) * 16;

    int aM = tid & 127, aKq = tid >> 7;
    int bR = tid >> 4, bC = tid & 15;                     // 16 rows x 16 col-quads
    const float* aBase = X + (long long)rowTok[aM] * K;

    float accG[4][2][4], accU[4][2][4];
#pragma unroll
    for (int i = 0; i < 4; i++)
#pragma unroll
        for (int j = 0; j < 2; j++)
#pragma unroll
            for (int q = 0; q < 4; q++) { accG[i][j][q] = 0.f; accU[i][j][q] = 0.f; }

    int KT = K / 16;
    {
        float4 a0 = *(const float4*)(aBase + aKq * 4);
        float4 a1 = *(const float4*)(aBase + (aKq + 2) * 4);
        float4 bg = *(const float4*)(Wgb + (long long)bR * N + n0 + bC * 4);
        float4 bu = *(const float4*)(Wub + (long long)bR * N + n0 + bC * 4);
        float* as = &As[0][aM * LDAS];
        *(float4*)(as + aKq * 4)       = make_float4(tf32r(a0.x), tf32r(a0.y), tf32r(a0.z), tf32r(a0.w));
        *(float4*)(as + (aKq + 2) * 4) = make_float4(tf32r(a1.x), tf32r(a1.y), tf32r(a1.z), tf32r(a1.w));
        *(float4*)&Bgs[0][bR * LDBSG + bC * 4] = make_float4(tf32r(bg.x), tf32r(bg.y), tf32r(bg.z), tf32r(bg.w));
        *(float4*)&Bus[0][bR * LDBSG + bC * 4] = make_float4(tf32r(bu.x), tf32r(bu.y), tf32r(bu.z), tf32r(bu.w));
    }
    __syncthreads();

    int buf = 0;
    for (int kt = 0; kt < KT; kt++) {
        bool hn = (kt + 1 < KT);
        float4 a0, a1, bg, bu;
        if (hn) {
            int k0 = (kt + 1) * 16;
            a0 = *(const float4*)(aBase + k0 + aKq * 4);
            a1 = *(const float4*)(aBase + k0 + (aKq + 2) * 4);
            bg = *(const float4*)(Wgb + (long long)(k0 + bR) * N + n0 + bC * 4);
            bu = *(const float4*)(Wub + (long long)(k0 + bR) * N + n0 + bC * 4);
        }
#pragma unroll
        for (int ks = 0; ks < 2; ks++) {
            uint32_t afr[4][4], bgf[2][2], buf2[2][2];
#pragma unroll
            for (int i = 0; i < 4; i++) {
                const float* ar = &As[buf][(warpM + i * 16 + g) * LDAS + ks * 8 + tc];
                afr[i][0] = __float_as_uint(ar[0]);
                afr[i][1] = __float_as_uint(ar[8 * LDAS]);
                afr[i][2] = __float_as_uint(ar[4]);
                afr[i][3] = __float_as_uint(ar[8 * LDAS + 4]);
            }
#pragma unroll
            for (int j = 0; j < 2; j++) {
                const float* bgr = &Bgs[buf][(ks * 8 + tc) * LDBSG + warpN + j * 8 + g];
                const float* bur = &Bus[buf][(ks * 8 + tc) * LDBSG + warpN + j * 8 + g];
                bgf[j][0] = __float_as_uint(bgr[0]);
                bgf[j][1] = __float_as_uint(bgr[4 * LDBSG]);
                buf2[j][0] = __float_as_uint(bur[0]);
                buf2[j][1] = __float_as_uint(bur[4 * LDBSG]);
            }
#pragma unroll
            for (int i = 0; i < 4; i++)
#pragma unroll
                for (int j = 0; j < 2; j++) {
                    mma_tf32(accG[i][j], afr[i], bgf[j]);
                    mma_tf32(accU[i][j], afr[i], buf2[j]);
                }
        }
        if (hn) {
            float* as = &As[buf ^ 1][aM * LDAS];
            *(float4*)(as + aKq * 4)       = make_float4(tf32r(a0.x), tf32r(a0.y), tf32r(a0.z), tf32r(a0.w));
            *(float4*)(as + (aKq + 2) * 4) = make_float4(tf32r(a1.x), tf32r(a1.y), tf32r(a1.z), tf32r(a1.w));
            *(float4*)&Bgs[buf ^ 1][bR * LDBSG + bC * 4] = make_float4(tf32r(bg.x), tf32r(bg.y), tf32r(bg.z), tf32r(bg.w));
            *(float4*)&Bus[buf ^ 1][bR * LDBSG + bC * 4] = make_float4(tf32r(bu.x), tf32r(bu.y), tf32r(bu.z), tf32r(bu.w));
        }
        __syncthreads();
        buf ^= 1;
    }

#pragma unroll
    for (int i = 0; i < 4; i++) {
#pragma unroll
        for (int half = 0; half < 2; half++) {
            int rr = warpM + i * 16 + g + half * 8;
            if (m0 + rr >= mc) continue;
            int pid = rowPid[rr];
            float* op = Out + (long long)pid * ldout + n0 + warpN + 2 * tc;
#pragma unroll
            for (int j = 0; j < 2; j++) {
                float g0 = accG[i][j][half * 2 + 0], g1 = accG[i][j][half * 2 + 1];
                float u0 = accU[i][j][half * 2 + 0], u1 = accU[i][j][half * 2 + 1];
                float v0 = (g0 / (1.f + expf(-g0))) * u0;
                float v1 = (g1 / (1.f + expf(-g1))) * u1;
                *(float2*)(op + j * 8) = make_float2(v0, v1);
            }
        }
    }
}

// ---------------- host ----------------
extern "C" void kernel_launch(void* const* d_in, const int* in_sizes, int n_in,
                              void* d_out, int out_size) {
    const float* hidden = (const float*)d_in[0];
    const float* ln1w   = (const float*)d_in[1];
    const float* ln2w   = (const float*)d_in[2];
    const float* qnw    = (const float*)d_in[3];
    const float* knw    = (const float*)d_in[4];
    const float* Wq     = (const float*)d_in[5];
    const float* Wk     = (const float*)d_in[6];
    const float* Wv     = (const float*)d_in[7];
    const float* Wo     = (const float*)d_in[8];
    const float* Wr     = (const float*)d_in[9];
    const float* Weg    = (const float*)d_in[10];
    const float* Weu    = (const float*)d_in[11];
    const float* Wed    = (const float*)d_in[12];
    const float* Wsg    = (const float*)d_in[13];
    const float* Wsu    = (const float*)d_in[14];
    const float* Wsd    = (const float*)d_in[15];
    const float* Wshg   = (const float*)d_in[16];
    float* out = (float*)d_out;

    float *x, *q, *kb, *vb, *sc, *o, *h, *x2, *act, *ys, *acts, *shr, *sig, *pw;
    int *cnt, *cntT, *ptok, *ppid, *idl;
    cudaGetSymbolAddress((void**)&x,    g_x);
    cudaGetSymbolAddress((void**)&q,    g_q);
    cudaGetSymbolAddress((void**)&kb,   g_kbuf);
    cudaGetSymbolAddress((void**)&vb,   g_vbuf);
    cudaGetSymbolAddress((void**)&sc,   g_sc);
    cudaGetSymbolAddress((void**)&o,    g_o);
    cudaGetSymbolAddress((void**)&h,    g_h);
    cudaGetSymbolAddress((void**)&x2,   g_x2);
    cudaGetSymbolAddress((void**)&act,  g_act);
    cudaGetSymbolAddress((void**)&ys,   g_ys);
    cudaGetSymbolAddress((void**)&acts, g_acts);
    cudaGetSymbolAddress((void**)&shr,  g_shr);
    cudaGetSymbolAddress((void**)&sig,  g_sig);
    cudaGetSymbolAddress((void**)&pw,   g_pw);
    cudaGetSymbolAddress((void**)&cnt,  g_cnt);
    cudaGetSymbolAddress((void**)&cntT, g_cntT);
    cudaGetSymbolAddress((void**)&ptok, g_ptok);
    cudaGetSymbolAddress((void**)&ppid, g_ppid);
    cudaGetSymbolAddress((void**)&idl,  g_idl);

    const float scale = 0.08838834764831845f;   // D^-0.5

    // 1) ln1
    rmsnorm_k<<<TT, 256>>>(hidden, ln1w, x, HH);
    // 2) q,k,v projections (tf32 tensor cores)
    tmm_k<<<dim3(32, 32, 1), 256>>>(x, Wq, q, nullptr, nullptr, nullptr, nullptr, TT,
        NHQ * DH, HH, HH, NHQ * DH, 0, 0);
    tmm_k<<<dim3(4, 32, 1), 256>>>(x, Wk, kb, nullptr, nullptr, nullptr, nullptr, TT,
        NKV * DH, HH, HH, NKV * DH, 0, 0);
    tmm_k<<<dim3(4, 32, 1), 256>>>(x, Wv, vb, nullptr, nullptr, nullptr, nullptr, TT,
        NKV * DH, HH, HH, NKV * DH, 0, 0);
    // 3) q/k rmsnorm + rope
    qknorm_rope_k<<<TT * NHQ, DH>>>(q, qnw, NHQ);
    qknorm_rope_k<<<TT * NKV, DH>>>(kb, knw, NKV);
    // 4) scores = scale * q @ k^T (fp32, causal tile-skip), batched over B*NH
    sgemm_k<true><<<dim3(8, 8, BB * NHQ), 256>>>(q, kb, sc, nullptr, SS, SS, DH,
        NHQ*DH, NKV*DH, SS,
        (long long)SS*NHQ*DH, DH,
        (long long)SS*NKV*DH, DH,
        0, 0, (long long)SS*SS,
        NHQ, GQA, scale, 2);
    // 5) causal softmax
    softmax_k<<<BB * NHQ * SS, 256>>>(sc);
    // 6) o = p @ v (fp32, causal K bound)
    sgemm_k<false><<<dim3(1, 8, BB * NHQ), 256>>>(sc, vb, o, nullptr, SS, DH, SS,
        SS, NKV*DH, NHQ*DH,
        (long long)NHQ*SS*SS, (long long)SS*SS,
        (long long)SS*NKV*DH, DH,
        (long long)SS*NHQ*DH, DH, 0,
        NHQ, GQA, 1.f, 4);
    // 7) h = hidden + o @ Wo (tf32)
    tmm_k<<<dim3(16, 32, 1), 256>>>(o, Wo, h, hidden, nullptr, nullptr, nullptr, TT,
        HH, NHQ * DH, NHQ * DH, HH, 0, 0);
    // 8) ln2
    rmsnorm_k<<<TT, 256>>>(h, ln2w, x2, HH);
    // 9) routing
    cudaMemsetAsync(cnt, 0, NE * sizeof(int), 0);
    init_k<<<TT / 256, 256>>>(idl, cntT);
    router_k<<<TT, 128>>>(x2, Wr, cnt, ptok, ppid, pw);
    // 10) MoE experts (tf32): gate/up (silu fused) then down (weighted, per-slot)
    tgu_k<<<dim3(II / 64, 32, NE), 256>>>(x2, Weg, Weu, act, ptok, ppid, cnt, 0,
        II, HH, (long long)HH * II, II, TT);
    tmm_k<<<dim3(HH / 128, 32, NE), 256>>>(act, Wed, ys, nullptr, ppid, pw, cnt, 0,
        HH, II, II, HH, (long long)II * HH, TT);
    // 11) shared expert (tf32) via identity lists
    tgu_k<<<dim3(ISD / 64, 32, 1), 256>>>(x2, Wsg, Wsu, acts, idl, idl, cntT, 0,
        ISD, HH, 0, ISD, TT);
    tmm_k<<<dim3(HH / 128, 32, 1), 256>>>(acts, Wsd, shr, nullptr, idl, nullptr, cntT, 0,
        HH, ISD, ISD, HH, 0, TT);
    sig_k<<<TT, 256>>>(x2, Wshg, sig);
    // 12) out = h + sum(slots) + shared*sigmoid
    final_k<<<(TT * HH) / 256, 256>>>(h, ys, shr, sig, out);
}

// round 7
// speedup vs baseline: 2.7254x; 1.2017x over previous
#include <cuda_runtime.h>
#include <cstdint>

// ---------------- problem dims ----------------
#define BB   4
#define SS   1024
#define HH   2048
#define NHQ  32
#define NKV  4
#define DH   128
#define NE   32
#define TOPK 8
#define II   768
#define ISD  4096
#define TT   4096          // B*S tokens
#define GQA  8             // NHQ/NKV

// ---------------- scratch (static __device__, no allocs) ----------------
static __device__ float g_x    [(size_t)TT*HH];          // ln1 out
static __device__ float g_q    [(size_t)TT*NHQ*DH];
static __device__ float g_kbuf [(size_t)TT*NKV*DH];
static __device__ float g_vbuf [(size_t)TT*NKV*DH];
static __device__ float g_o    [(size_t)TT*NHQ*DH];
static __device__ float g_h    [(size_t)TT*HH];          // residual after attn
static __device__ float g_x2   [(size_t)TT*HH];          // ln2 out
static __device__ float g_act  [(size_t)TT*TOPK*II];     // moe gate*up
static __device__ float g_ys   [(size_t)TT*TOPK*HH];     // per-slot expert out
static __device__ float g_acts [(size_t)TT*ISD];         // shared gate*up
static __device__ float g_shr  [(size_t)TT*HH];          // shared expert out
static __device__ float g_sig  [TT];
static __device__ int   g_cnt  [NE];
static __device__ int   g_cntT [1];
static __device__ int   g_ptok [(size_t)NE*TT];
static __device__ int   g_ppid [(size_t)NE*TT];
static __device__ float g_pw   [(size_t)NE*TT];
static __device__ int   g_idl  [TT];

// ---------------- helpers ----------------
__device__ __forceinline__ float blockReduceSum(float v) {
    __shared__ float sh[32];
    int lane = threadIdx.x & 31, wid = threadIdx.x >> 5;
#pragma unroll
    for (int o = 16; o > 0; o >>= 1) v += __shfl_xor_sync(0xffffffffu, v, o);
    if (lane == 0) sh[wid] = v;
    __syncthreads();
    int nw = blockDim.x >> 5;
    v = (threadIdx.x < nw) ? sh[threadIdx.x] : 0.f;
    if (wid == 0) {
#pragma unroll
        for (int o = 16; o > 0; o >>= 1) v += __shfl_xor_sync(0xffffffffu, v, o);
        if (lane == 0) sh[0] = v;
    }
    __syncthreads();
    v = sh[0];
    __syncthreads();
    return v;
}

// tf32 helpers
__device__ __forceinline__ float tf32r(float x) {
    uint32_t r;
    asm("cvt.rna.tf32.f32 %0, %1;" : "=r"(r) : "f"(x));
    return __uint_as_float(r);
}
__device__ __forceinline__ float4 tf32r4(float4 v) {
    return make_float4(tf32r(v.x), tf32r(v.y), tf32r(v.z), tf32r(v.w));
}
__device__ __forceinline__ void mma_tf32(float* c, const uint32_t* a, const uint32_t* b) {
    asm volatile(
        "mma.sync.aligned.m16n8k8.row.col.f32.tf32.tf32.f32 "
        "{%0,%1,%2,%3}, {%4,%5,%6,%7}, {%8,%9}, {%0,%1,%2,%3};\n"
        : "+f"(c[0]), "+f"(c[1]), "+f"(c[2]), "+f"(c[3])
        : "r"(a[0]), "r"(a[1]), "r"(a[2]), "r"(a[3]), "r"(b[0]), "r"(b[1]));
}
__device__ __forceinline__ float ex2f(float x) {
    float r; asm("ex2.approx.ftz.f32 %0, %1;" : "=f"(r) : "f"(x)); return r;
}

// cp.async helpers
__device__ __forceinline__ void cp16(uint32_t s, const void* g) {
    asm volatile("cp.async.ca.shared.global [%0], [%1], 16;\n" :: "r"(s), "l"(g));
}
__device__ __forceinline__ void cp_commit() { asm volatile("cp.async.commit_group;\n"); }
template<int N> __device__ __forceinline__ void cp_wait() {
    asm volatile("cp.async.wait_group %0;\n" :: "n"(N));
}

// ---------------- elementwise / norm kernels ----------------
__global__ void rmsnorm_k(const float* __restrict__ in, const float* __restrict__ w,
                          float* __restrict__ out, int ncols) {
    long long row = blockIdx.x;
    const float* x = in + row * (long long)ncols;
    float* o = out + row * (long long)ncols;
    float s = 0.f;
    for (int i = threadIdx.x; i < ncols; i += blockDim.x) { float v = x[i]; s += v * v; }
    s = blockReduceSum(s);
    float r = rsqrtf(s / (float)ncols + 1e-6f);
    for (int i = threadIdx.x; i < ncols; i += blockDim.x) o[i] = x[i] * r * w[i];
}

// per-(token,head) rmsnorm over D=128, then NeoX RoPE. blockDim=128
__global__ void qknorm_rope_k(float* __restrict__ qk, const float* __restrict__ w, int nheads) {
    int idx = blockIdx.x;            // t*nheads + h
    int t = idx / nheads;
    int pos = t & (SS - 1);          // s within batch
    float* x = qk + (size_t)idx * DH;
    int d = threadIdx.x;
    float v = x[d];
    float ss = v * v;
#pragma unroll
    for (int o = 16; o > 0; o >>= 1) ss += __shfl_xor_sync(0xffffffffu, ss, o);
    __shared__ float wsum[4];
    if ((d & 31) == 0) wsum[d >> 5] = ss;
    __syncthreads();
    float tot = wsum[0] + wsum[1] + wsum[2] + wsum[3];
    float r = rsqrtf(tot * (1.0f / DH) + 1e-6f);
    float xn = v * r * w[d];
    __shared__ float xs[DH];
    xs[d] = xn;
    __syncthreads();
    int fi = d & 63;
    float ang = (float)pos * expf(-0.215867352778f * (float)fi);
    float c = cosf(ang), s = sinf(ang);
    float rot = (d < 64) ? -xs[d + 64] : xs[d - 64];
    x[d] = xn * c + rot * s;
}

__global__ void init_k(int* __restrict__ idl, int* __restrict__ cntT) {
    int i = blockIdx.x * blockDim.x + threadIdx.x;
    if (i < TT) idl[i] = i;
    if (i == 0) cntT[0] = TT;
}

// router: logits = x2 @ Wr, softmax, top-8, normalize, append to expert lists. blockDim=128
__global__ void router_k(const float* __restrict__ X, const float* __restrict__ Wr,
                         int* __restrict__ cnt, int* __restrict__ gtok,
                         int* __restrict__ gpid, float* __restrict__ gpw) {
    int t = blockIdx.x;
    const float* x = X + (size_t)t * HH;
    float part[NE];
#pragma unroll
    for (int e = 0; e < NE; e++) part[e] = 0.f;
    for (int k = threadIdx.x; k < HH; k += 128) {
        float xv = x[k];
        const float* wr = Wr + (size_t)k * NE;
#pragma unroll
        for (int e = 0; e < NE; e++) part[e] += xv * wr[e];
    }
    __shared__ float sh[NE * 128];
#pragma unroll
    for (int e = 0; e < NE; e++) sh[e * 128 + threadIdx.x] = part[e];
    __syncthreads();
    __shared__ float logits[NE];
    if (threadIdx.x < NE) {
        float s = 0.f;
        for (int i = 0; i < 128; i++) s += sh[threadIdx.x * 128 + i];
        logits[threadIdx.x] = s;
    }
    __syncthreads();
    if (threadIdx.x == 0) {
        float mx = -3.0e38f;
        for (int e = 0; e < NE; e++) mx = fmaxf(mx, logits[e]);
        float p[NE], se = 0.f;
        for (int e = 0; e < NE; e++) { p[e] = expf(logits[e] - mx); se += p[e]; }
        float inv = 1.f / se;
        for (int e = 0; e < NE; e++) p[e] *= inv;
        int idx[TOPK]; float val[TOPK]; float vs = 0.f;
        bool used[NE];
        for (int e = 0; e < NE; e++) used[e] = false;
        for (int s = 0; s < TOPK; s++) {
            float bv = -1.f; int bi = 0;
            for (int e = 0; e < NE; e++)
                if (!used[e] && p[e] > bv) { bv = p[e]; bi = e; }
            used[bi] = true; idx[s] = bi; val[s] = bv; vs += bv;
        }
        float invs = 1.f / vs;
        for (int s = 0; s < TOPK; s++) {
            int e = idx[s];
            int pos = atomicAdd(&cnt[e], 1);
            gtok[(size_t)e * TT + pos] = t;
            gpid[(size_t)e * TT + pos] = t * TOPK + s;
            gpw [(size_t)e * TT + pos] = val[s] * invs;
        }
    }
}

__global__ void sig_k(const float* __restrict__ X, const float* __restrict__ Wshg,
                      float* __restrict__ sig) {
    int t = blockIdx.x;
    const float* x = X + (size_t)t * HH;
    float s = 0.f;
    for (int i = threadIdx.x; i < HH; i += blockDim.x) s += x[i] * Wshg[i];
    s = blockReduceSum(s);
    if (threadIdx.x == 0) sig[t] = 1.f / (1.f + expf(-s));
}

__global__ void final_k(const float* __restrict__ h, const float* __restrict__ ys,
                        const float* __restrict__ shr, const float* __restrict__ sig,
                        float* __restrict__ out) {
    long long idx = (long long)blockIdx.x * 256 + threadIdx.x;
    if (idx >= (long long)TT * HH) return;
    int t = (int)(idx >> 11);
    int n = (int)(idx & (HH - 1));
    float s = h[idx];
    const float* yr = ys + ((long long)t * TOPK) * HH + n;
#pragma unroll
    for (int k = 0; k < TOPK; k++) s += yr[(long long)k * HH];
    s += shr[idx] * sig[t];
    out[idx] = s;
}

// ================= TF32 tensor-core GEMM, cp.async 3-stage =================
// BM=128, BN=128, BK=16, 256 threads (2m x 4n warps), warp tile 64x32.
#define LDAS 20
#define LDBS 132
#define NST  3
#define TMM_SMEM ((NST*128*LDAS + NST*16*LDBS)*4)

__global__ void __launch_bounds__(256, 2)
tmm_k(const float* __restrict__ A, const float* __restrict__ Bm,
      float* __restrict__ C, const float* __restrict__ addC,
      const int* __restrict__ rows, const float* __restrict__ wgt,
      const int* __restrict__ cnt, int Mfix,
      int N, int K, int lda, int ldc, long long bstride, int listld) {
    extern __shared__ float sm[];
    float* As = sm;                        // [NST][128*LDAS]
    float* Bs = sm + NST * 128 * LDAS;     // [NST][16*LDBS]
    __shared__ int   rowIdx[128];
    __shared__ float rowW[128];

    int z = blockIdx.z;
    int mc = cnt ? cnt[z] : Mfix;
    int m0 = blockIdx.y * 128;
    if (m0 >= mc) return;
    int n0 = blockIdx.x * 128;
    const float* Bb = Bm + (long long)z * bstride;
    const int*   rl = rows ? rows + (long long)z * listld : nullptr;
    const float* wl = wgt  ? wgt  + (long long)z * listld : nullptr;

    int tid = threadIdx.x;
    if (tid < 128) {
        int m = min(m0 + tid, mc - 1);
        rowIdx[tid] = rl ? rl[m] : m;
        rowW[tid]   = wl ? wl[m] : 1.f;
    }
    __syncthreads();

    int warp = tid >> 5, lane = tid & 31;
    int g = lane >> 2, tc = lane & 3;
    int warpM = (warp & 1) * 64, warpN = (warp >> 1) * 32;

    int aM = tid & 127, aKq = tid >> 7;
    int bR = tid >> 5,  bC = tid & 31;
    const float* aBase = A + (long long)rowIdx[aM] * lda;
    uint32_t asA = (uint32_t)__cvta_generic_to_shared(As);
    uint32_t bsA = (uint32_t)__cvta_generic_to_shared(Bs);
    uint32_t aS0 = asA + (uint32_t)(aM * LDAS + aKq * 4) * 4u;
    uint32_t aS1 = asA + (uint32_t)(aM * LDAS + (aKq + 2) * 4) * 4u;
    uint32_t bS0 = bsA + (uint32_t)(bR * LDBS + bC * 4) * 4u;
    uint32_t bS1 = bsA + (uint32_t)((bR + 8) * LDBS + bC * 4) * 4u;
    const uint32_t aStep = 128u * LDAS * 4u, bStep = 16u * LDBS * 4u;

    float acc[4][4][4] = {};
    int KT = K / 16;

#define TMM_ISSUE(kt, buf) { \
        int k0_ = (kt) * 16; \
        cp16(aS0 + (buf) * aStep, aBase + k0_ + aKq * 4); \
        cp16(aS1 + (buf) * aStep, aBase + k0_ + (aKq + 2) * 4); \
        cp16(bS0 + (buf) * bStep, Bb + (long long)(k0_ + bR) * N + n0 + bC * 4); \
        cp16(bS1 + (buf) * bStep, Bb + (long long)(k0_ + bR + 8) * N + n0 + bC * 4); \
        cp_commit(); }

    TMM_ISSUE(0, 0);
    TMM_ISSUE(1, 1);

    for (int kt = 0; kt < KT; kt++) {
        int nb = kt + NST - 1;
        if (nb < KT) { TMM_ISSUE(nb, nb % NST); cp_wait<NST - 2>(); }
        else cp_wait<0>();
        __syncthreads();
        const float* Ab2 = As + (kt % NST) * 128 * LDAS;
        const float* Bb2 = Bs + (kt % NST) * 16 * LDBS;
#pragma unroll
        for (int ks = 0; ks < 2; ks++) {
            uint32_t afr[4][4], bfr[4][2];
#pragma unroll
            for (int i = 0; i < 4; i++) {
                const float* ar = Ab2 + (warpM + i * 16 + g) * LDAS + ks * 8 + tc;
                afr[i][0] = __float_as_uint(tf32r(ar[0]));
                afr[i][1] = __float_as_uint(tf32r(ar[8 * LDAS]));
                afr[i][2] = __float_as_uint(tf32r(ar[4]));
                afr[i][3] = __float_as_uint(tf32r(ar[8 * LDAS + 4]));
            }
#pragma unroll
            for (int j = 0; j < 4; j++) {
                const float* br = Bb2 + (ks * 8 + tc) * LDBS + warpN + j * 8 + g;
                bfr[j][0] = __float_as_uint(tf32r(br[0]));
                bfr[j][1] = __float_as_uint(tf32r(br[4 * LDBS]));
            }
#pragma unroll
            for (int i = 0; i < 4; i++)
#pragma unroll
                for (int j = 0; j < 4; j++) mma_tf32(acc[i][j], afr[i], bfr[j]);
        }
        __syncthreads();
    }

#pragma unroll
    for (int i = 0; i < 4; i++) {
#pragma unroll
        for (int half = 0; half < 2; half++) {
            int rr = warpM + i * 16 + g + half * 8;
            if (m0 + rr >= mc) continue;
            int grow = rowIdx[rr];
            float w = rowW[rr];
            float* cp = C + (long long)grow * ldc + n0 + warpN + 2 * tc;
            const float* ap = addC ? addC + (long long)grow * ldc + n0 + warpN + 2 * tc : nullptr;
#pragma unroll
            for (int j = 0; j < 4; j++) {
                float v0 = acc[i][j][half * 2 + 0] * w;
                float v1 = acc[i][j][half * 2 + 1] * w;
                if (ap) {
                    float2 c0 = *(const float2*)(ap + j * 8);
                    v0 += c0.x; v1 += c0.y;
                }
                *(float2*)(cp + j * 8) = make_float2(v0, v1);
            }
        }
    }
}

// ================= TF32 grouped gate/up GEMM, cp.async 3-stage =================
// BM=128, BN=64, BK=16, 256 threads (2m x 4n warps), warp tile 64x16.
#define LDBSG 68
#define TGU_SMEM ((NST*128*LDAS + NST*16*LDBSG*2)*4)

__global__ void __launch_bounds__(256, 2)
tgu_k(const float* __restrict__ X,
      const float* __restrict__ Wg, const float* __restrict__ Wu,
      float* __restrict__ Out,
      const int* __restrict__ gtok, const int* __restrict__ gpid,
      const int* __restrict__ cnt, int Mfix,
      int N, int K, long long wstride, int ldout, int listld) {
    extern __shared__ float sm[];
    float* As  = sm;                            // [NST][128*LDAS]
    float* Bgs = sm + NST * 128 * LDAS;         // [NST][16*LDBSG]
    float* Bus = Bgs + NST * 16 * LDBSG;        // [NST][16*LDBSG]
    __shared__ int rowTok[128];
    __shared__ int rowPid[128];

    int z = blockIdx.z;
    int mc = cnt ? cnt[z] : Mfix;
    int m0 = blockIdx.y * 128;
    if (m0 >= mc) return;
    int n0 = blockIdx.x * 64;
    const float* Wgb = Wg + (long long)z * wstride;
    const float* Wub = Wu + (long long)z * wstride;
    const int* lt = gtok + (long long)z * listld;
    const int* lp = gpid + (long long)z * listld;

    int tid = threadIdx.x;
    if (tid < 128) {
        int m = min(m0 + tid, mc - 1);
        rowTok[tid] = lt[m];
        rowPid[tid] = lp[m];
    }
    __syncthreads();

    int warp = tid >> 5, lane = tid & 31;
    int g = lane >> 2, tc = lane & 3;
    int warpM = (warp & 1) * 64, warpN = (warp >> 1) * 16;

    int aM = tid & 127, aKq = tid >> 7;
    int bR = tid >> 4, bC = tid & 15;
    const float* aBase = X + (long long)rowTok[aM] * K;
    uint32_t asA = (uint32_t)__cvta_generic_to_shared(As);
    uint32_t bgA = (uint32_t)__cvta_generic_to_shared(Bgs);
    uint32_t buA = (uint32_t)__cvta_generic_to_shared(Bus);
    uint32_t aS0 = asA + (uint32_t)(aM * LDAS + aKq * 4) * 4u;
    uint32_t aS1 = asA + (uint32_t)(aM * LDAS + (aKq + 2) * 4) * 4u;
    uint32_t bOf = (uint32_t)(bR * LDBSG + bC * 4) * 4u;
    const uint32_t aStep = 128u * LDAS * 4u, bStep = 16u * LDBSG * 4u;

    float accG[4][2][4] = {}, accU[4][2][4] = {};
    int KT = K / 16;

#define TGU_ISSUE(kt, buf) { \
        int k0_ = (kt) * 16; \
        cp16(aS0 + (buf) * aStep, aBase + k0_ + aKq * 4); \
        cp16(aS1 + (buf) * aStep, aBase + k0_ + (aKq + 2) * 4); \
        cp16(bgA + bOf + (buf) * bStep, Wgb + (long long)(k0_ + bR) * N + n0 + bC * 4); \
        cp16(buA + bOf + (buf) * bStep, Wub + (long long)(k0_ + bR) * N + n0 + bC * 4); \
        cp_commit(); }

    TGU_ISSUE(0, 0);
    TGU_ISSUE(1, 1);

    for (int kt = 0; kt < KT; kt++) {
        int nb = kt + NST - 1;
        if (nb < KT) { TGU_ISSUE(nb, nb % NST); cp_wait<NST - 2>(); }
        else cp_wait<0>();
        __syncthreads();
        const float* Ab2 = As + (kt % NST) * 128 * LDAS;
        const float* Bg2 = Bgs + (kt % NST) * 16 * LDBSG;
        const float* Bu2 = Bus + (kt % NST) * 16 * LDBSG;
#pragma unroll
        for (int ks = 0; ks < 2; ks++) {
            uint32_t afr[4][4], bgf[2][2], buf2[2][2];
#pragma unroll
            for (int i = 0; i < 4; i++) {
                const float* ar = Ab2 + (warpM + i * 16 + g) * LDAS + ks * 8 + tc;
                afr[i][0] = __float_as_uint(tf32r(ar[0]));
                afr[i][1] = __float_as_uint(tf32r(ar[8 * LDAS]));
                afr[i][2] = __float_as_uint(tf32r(ar[4]));
                afr[i][3] = __float_as_uint(tf32r(ar[8 * LDAS + 4]));
            }
#pragma unroll
            for (int j = 0; j < 2; j++) {
                const float* bgr = Bg2 + (ks * 8 + tc) * LDBSG + warpN + j * 8 + g;
                const float* bur = Bu2 + (ks * 8 + tc) * LDBSG + warpN + j * 8 + g;
                bgf[j][0] = __float_as_uint(tf32r(bgr[0]));
                bgf[j][1] = __float_as_uint(tf32r(bgr[4 * LDBSG]));
                buf2[j][0] = __float_as_uint(tf32r(bur[0]));
                buf2[j][1] = __float_as_uint(tf32r(bur[4 * LDBSG]));
            }
#pragma unroll
            for (int i = 0; i < 4; i++)
#pragma unroll
                for (int j = 0; j < 2; j++) {
                    mma_tf32(accG[i][j], afr[i], bgf[j]);
                    mma_tf32(accU[i][j], afr[i], buf2[j]);
                }
        }
        __syncthreads();
    }

#pragma unroll
    for (int i = 0; i < 4; i++) {
#pragma unroll
        for (int half = 0; half < 2; half++) {
            int rr = warpM + i * 16 + g + half * 8;
            if (m0 + rr >= mc) continue;
            int pid = rowPid[rr];
            float* op = Out + (long long)pid * ldout + n0 + warpN + 2 * tc;
#pragma unroll
            for (int j = 0; j < 2; j++) {
                float g0 = accG[i][j][half * 2 + 0], g1 = accG[i][j][half * 2 + 1];
                float u0 = accU[i][j][half * 2 + 0], u1 = accU[i][j][half * 2 + 1];
                float v0 = (g0 / (1.f + expf(-g0))) * u0;
                float v1 = (g1 / (1.f + expf(-g1))) * u1;
                *(float2*)(op + j * 8) = make_float2(v0, v1);
            }
        }
    }
}

// ================= Fused flash attention (tf32 MMA, online softmax) =================
// One block per (b, head, 128-query tile). 8 warps, each owns 16 query rows.
// KV tiles of 64 keys, double-buffered cp.async; causal.
#define FLDK 132
#define FLDP 68
#define FLASH_SMEM ((4*64*FLDK + 8*16*FLDP)*4)

__global__ void __launch_bounds__(256)
flash_k(const float* __restrict__ Q, const float* __restrict__ Kb,
        const float* __restrict__ Vb, float* __restrict__ O) {
    extern __shared__ float fs[];
    float* Ks = fs;                       // [2][64][FLDK]
    float* Vs = fs + 2 * 64 * FLDK;       // [2][64][FLDK]
    float* Ps = fs + 4 * 64 * FLDK;       // [8][16][FLDP]

    int bh = blockIdx.x;                  // b*NHQ + h
    int b = bh >> 5, hq = bh & 31;
    int kvh = hq >> 3;                    // GQA
    int qb = 7 - blockIdx.y;              // big tiles first
    int tid = threadIdx.x, w = tid >> 5, lane = tid & 31;
    int g = lane >> 2, tc = lane & 3;

    int row0 = qb * 128 + w * 16 + g;
    int row1 = row0 + 8;
    const float* q0 = Q + ((long long)(b * SS + row0) * NHQ + hq) * DH;
    const float* q1 = q0 + (long long)8 * NHQ * DH;
    const float* kbase = Kb + ((long long)b * SS * NKV + kvh) * DH;
    const float* vbase = Vb + ((long long)b * SS * NKV + kvh) * DH;
    uint32_t ksA = (uint32_t)__cvta_generic_to_shared(Ks);
    uint32_t vsA = (uint32_t)__cvta_generic_to_shared(Vs);

    const float scale = 0.08838834764831845f;   // D^-0.5, folded into Q
    uint32_t qf[16][4];
#pragma unroll
    for (int kk = 0; kk < 16; kk++) {
        qf[kk][0] = __float_as_uint(tf32r(q0[kk * 8 + tc] * scale));
        qf[kk][1] = __float_as_uint(tf32r(q1[kk * 8 + tc] * scale));
        qf[kk][2] = __float_as_uint(tf32r(q0[kk * 8 + tc + 4] * scale));
        qf[kk][3] = __float_as_uint(tf32r(q1[kk * 8 + tc + 4] * scale));
    }

    float o[16][4] = {};
    float m0 = -1e30f, m1 = -1e30f, l0 = 0.f, l1 = 0.f;
    float* Pw = Ps + w * 16 * FLDP;
    const float L2E = 1.4426950408889634f;

    int NT = (qb + 1) * 2;

#define FL_LOAD(n0_, buf_) { \
        _Pragma("unroll") \
        for (int p = 0; p < 8; p++) { \
            int c = tid + p * 256; \
            int r = c >> 5, cq = c & 31; \
            long long go = (long long)((n0_) + r) * (NKV * DH) + cq * 4; \
            uint32_t so = (uint32_t)((((buf_) * 64 + r) * FLDK + cq * 4) * 4); \
            cp16(ksA + so, kbase + go); \
            cp16(vsA + so, vbase + go); \
        } \
        cp_commit(); }

    FL_LOAD(0, 0);

    for (int jt = 0; jt < NT; jt++) {
        int n0 = jt * 64;
        if (jt + 1 < NT) { FL_LOAD((jt + 1) * 64, (jt + 1) & 1); cp_wait<1>(); }
        else cp_wait<0>();
        __syncthreads();

        float* Kt = Ks + (jt & 1) * 64 * FLDK;
        float* Vt = Vs + (jt & 1) * 64 * FLDK;
        // in-place tf32 conversion of the arrived tile
#pragma unroll
        for (int p = 0; p < 8; p++) {
            int c = tid + p * 256; int r = c >> 5, cq = c & 31;
            float4* kp = (float4*)(Kt + r * FLDK + cq * 4);
            float4* vp = (float4*)(Vt + r * FLDK + cq * 4);
            *kp = tf32r4(*kp);
            *vp = tf32r4(*vp);
        }
        __syncthreads();

        // S = Q K^T
        float s[8][4] = {};
#pragma unroll
        for (int kk = 0; kk < 16; kk++) {
#pragma unroll
            for (int j2 = 0; j2 < 8; j2++) {
                uint32_t bf[2];
                const float* kr = Kt + (j2 * 8 + g) * FLDK + kk * 8 + tc;
                bf[0] = __float_as_uint(kr[0]);
                bf[1] = __float_as_uint(kr[4]);
                mma_tf32(s[j2], qf[kk], bf);
            }
        }
        // causal mask for diagonal tiles
        if (n0 + 63 > qb * 128) {
#pragma unroll
            for (int j2 = 0; j2 < 8; j2++) {
                int k0 = n0 + j2 * 8 + 2 * tc;
                if (k0     > row0) s[j2][0] = -1e30f;
                if (k0 + 1 > row0) s[j2][1] = -1e30f;
                if (k0     > row1) s[j2][2] = -1e30f;
                if (k0 + 1 > row1) s[j2][3] = -1e30f;
            }
        }
        // online softmax (2 rows per thread)
        float tm0 = -1e30f, tm1 = -1e30f;
#pragma unroll
        for (int j2 = 0; j2 < 8; j2++) {
            tm0 = fmaxf(tm0, fmaxf(s[j2][0], s[j2][1]));
            tm1 = fmaxf(tm1, fmaxf(s[j2][2], s[j2][3]));
        }
        tm0 = fmaxf(tm0, __shfl_xor_sync(0xffffffffu, tm0, 1));
        tm0 = fmaxf(tm0, __shfl_xor_sync(0xffffffffu, tm0, 2));
        tm1 = fmaxf(tm1, __shfl_xor_sync(0xffffffffu, tm1, 1));
        tm1 = fmaxf(tm1, __shfl_xor_sync(0xffffffffu, tm1, 2));
        float mn0 = fmaxf(m0, tm0), mn1 = fmaxf(m1, tm1);
        float ts0 = 0.f, ts1 = 0.f;
#pragma unroll
        for (int j2 = 0; j2 < 8; j2++) {
            s[j2][0] = ex2f((s[j2][0] - mn0) * L2E);
            s[j2][1] = ex2f((s[j2][1] - mn0) * L2E);
            s[j2][2] = ex2f((s[j2][2] - mn1) * L2E);
            s[j2][3] = ex2f((s[j2][3] - mn1) * L2E);
            ts0 += s[j2][0] + s[j2][1];
            ts1 += s[j2][2] + s[j2][3];
        }
        ts0 += __shfl_xor_sync(0xffffffffu, ts0, 1);
        ts0 += __shfl_xor_sync(0xffffffffu, ts0, 2);
        ts1 += __shfl_xor_sync(0xffffffffu, ts1, 1);
        ts1 += __shfl_xor_sync(0xffffffffu, ts1, 2);
        float f0 = ex2f((m0 - mn0) * L2E), f1 = ex2f((m1 - mn1) * L2E);
        l0 = l0 * f0 + ts0; l1 = l1 * f1 + ts1;
        m0 = mn0; m1 = mn1;
#pragma unroll
        for (int j3 = 0; j3 < 16; j3++) {
            o[j3][0] *= f0; o[j3][1] *= f0; o[j3][2] *= f1; o[j3][3] *= f1;
        }
        // P -> smem (tf32), then O += P V
#pragma unroll
        for (int j2 = 0; j2 < 8; j2++) {
            Pw[g * FLDP + j2 * 8 + 2 * tc]           = tf32r(s[j2][0]);
            Pw[g * FLDP + j2 * 8 + 2 * tc + 1]       = tf32r(s[j2][1]);
            Pw[(g + 8) * FLDP + j2 * 8 + 2 * tc]     = tf32r(s[j2][2]);
            Pw[(g + 8) * FLDP + j2 * 8 + 2 * tc + 1] = tf32r(s[j2][3]);
        }
        __syncwarp();
#pragma unroll
        for (int kk2 = 0; kk2 < 8; kk2++) {
            uint32_t af[4];
            af[0] = __float_as_uint(Pw[g * FLDP + kk2 * 8 + tc]);
            af[1] = __float_as_uint(Pw[(g + 8) * FLDP + kk2 * 8 + tc]);
            af[2] = __float_as_uint(Pw[g * FLDP + kk2 * 8 + tc + 4]);
            af[3] = __float_as_uint(Pw[(g + 8) * FLDP + kk2 * 8 + tc + 4]);
#pragma unroll
            for (int j3 = 0; j3 < 16; j3++) {
                uint32_t bf[2];
                bf[0] = __float_as_uint(Vt[(kk2 * 8 + tc) * FLDK + j3 * 8 + g]);
                bf[1] = __float_as_uint(Vt[(kk2 * 8 + tc + 4) * FLDK + j3 * 8 + g]);
                mma_tf32(o[j3], af, bf);
            }
        }
        __syncwarp();
        __syncthreads();
    }

    float il0 = 1.f / l0, il1 = 1.f / l1;
    float* o0 = O + ((long long)(b * SS + row0) * NHQ + hq) * DH;
    float* o1 = o0 + (long long)8 * NHQ * DH;
#pragma unroll
    for (int j3 = 0; j3 < 16; j3++) {
        *(float2*)(o0 + j3 * 8 + 2 * tc) = make_float2(o[j3][0] * il0, o[j3][1] * il0);
        *(float2*)(o1 + j3 * 8 + 2 * tc) = make_float2(o[j3][2] * il1, o[j3][3] * il1);
    }
}

// ---------------- host ----------------
extern "C" void kernel_launch(void* const* d_in, const int* in_sizes, int n_in,
                              void* d_out, int out_size) {
    const float* hidden = (const float*)d_in[0];
    const float* ln1w   = (const float*)d_in[1];
    const float* ln2w   = (const float*)d_in[2];
    const float* qnw    = (const float*)d_in[3];
    const float* knw    = (const float*)d_in[4];
    const float* Wq     = (const float*)d_in[5];
    const float* Wk     = (const float*)d_in[6];
    const float* Wv     = (const float*)d_in[7];
    const float* Wo     = (const float*)d_in[8];
    const float* Wr     = (const float*)d_in[9];
    const float* Weg    = (const float*)d_in[10];
    const float* Weu    = (const float*)d_in[11];
    const float* Wed    = (const float*)d_in[12];
    const float* Wsg    = (const float*)d_in[13];
    const float* Wsu    = (const float*)d_in[14];
    const float* Wsd    = (const float*)d_in[15];
    const float* Wshg   = (const float*)d_in[16];
    float* out = (float*)d_out;

    float *x, *q, *kb, *vb, *o, *h, *x2, *act, *ys, *acts, *shr, *sig, *pw;
    int *cnt, *cntT, *ptok, *ppid, *idl;
    cudaGetSymbolAddress((void**)&x,    g_x);
    cudaGetSymbolAddress((void**)&q,    g_q);
    cudaGetSymbolAddress((void**)&kb,   g_kbuf);
    cudaGetSymbolAddress((void**)&vb,   g_vbuf);
    cudaGetSymbolAddress((void**)&o,    g_o);
    cudaGetSymbolAddress((void**)&h,    g_h);
    cudaGetSymbolAddress((void**)&x2,   g_x2);
    cudaGetSymbolAddress((void**)&act,  g_act);
    cudaGetSymbolAddress((void**)&ys,   g_ys);
    cudaGetSymbolAddress((void**)&acts, g_acts);
    cudaGetSymbolAddress((void**)&shr,  g_shr);
    cudaGetSymbolAddress((void**)&sig,  g_sig);
    cudaGetSymbolAddress((void**)&pw,   g_pw);
    cudaGetSymbolAddress((void**)&cnt,  g_cnt);
    cudaGetSymbolAddress((void**)&cntT, g_cntT);
    cudaGetSymbolAddress((void**)&ptok, g_ptok);
    cudaGetSymbolAddress((void**)&ppid, g_ppid);
    cudaGetSymbolAddress((void**)&idl,  g_idl);

    // set attributes unconditionally each call (cheap host calls; no static guards)
    cudaFuncSetAttribute(tmm_k,   cudaFuncAttributeMaxDynamicSharedMemorySize, TMM_SMEM);
    cudaFuncSetAttribute(tgu_k,   cudaFuncAttributeMaxDynamicSharedMemorySize, TGU_SMEM);
    cudaFuncSetAttribute(flash_k, cudaFuncAttributeMaxDynamicSharedMemorySize, FLASH_SMEM);

    // 1) ln1
    rmsnorm_k<<<TT, 256>>>(hidden, ln1w, x, HH);
    // 2) q,k,v projections (tf32 tensor cores, cp.async pipeline)
    tmm_k<<<dim3(32, 32, 1), 256, TMM_SMEM>>>(x, Wq, q, nullptr, nullptr, nullptr, nullptr, TT,
        NHQ * DH, HH, HH, NHQ * DH, 0, 0);
    tmm_k<<<dim3(4, 32, 1), 256, TMM_SMEM>>>(x, Wk, kb, nullptr, nullptr, nullptr, nullptr, TT,
        NKV * DH, HH, HH, NKV * DH, 0, 0);
    tmm_k<<<dim3(4, 32, 1), 256, TMM_SMEM>>>(x, Wv, vb, nullptr, nullptr, nullptr, nullptr, TT,
        NKV * DH, HH, HH, NKV * DH, 0, 0);
    // 3) q/k rmsnorm + rope
    qknorm_rope_k<<<TT * NHQ, DH>>>(q, qnw, NHQ);
    qknorm_rope_k<<<TT * NKV, DH>>>(kb, knw, NKV);
    // 4-6) fused flash attention (causal, online softmax)
    flash_k<<<dim3(BB * NHQ, 8), 256, FLASH_SMEM>>>(q, kb, vb, o);
    // 7) h = hidden + o @ Wo (tf32)
    tmm_k<<<dim3(16, 32, 1), 256, TMM_SMEM>>>(o, Wo, h, hidden, nullptr, nullptr, nullptr, TT,
        HH, NHQ * DH, NHQ * DH, HH, 0, 0);
    // 8) ln2
    rmsnorm_k<<<TT, 256>>>(h, ln2w, x2, HH);
    // 9) routing
    cudaMemsetAsync(cnt, 0, NE * sizeof(int), 0);
    init_k<<<TT / 256, 256>>>(idl, cntT);
    router_k<<<TT, 128>>>(x2, Wr, cnt, ptok, ppid, pw);
    // 10) MoE experts (tf32): gate/up (silu fused) then down (weighted, per-slot)
    tgu_k<<<dim3(II / 64, 32, NE), 256, TGU_SMEM>>>(x2, Weg, Weu, act, ptok, ppid, cnt, 0,
        II, HH, (long long)HH * II, II, TT);
    tmm_k<<<dim3(HH / 128, 32, NE), 256, TMM_SMEM>>>(act, Wed, ys, nullptr, ppid, pw, cnt, 0,
        HH, II, II, HH, (long long)II * HH, TT);
    // 11) shared expert (tf32) via identity lists
    tgu_k<<<dim3(ISD / 64, 32, 1), 256, TGU_SMEM>>>(x2, Wsg, Wsu, acts, idl, idl, cntT, 0,
        ISD, HH, 0, ISD, TT);
    tmm_k<<<dim3(HH / 128, 32, 1), 256, TMM_SMEM>>>(acts, Wsd, shr, nullptr, idl, nullptr, cntT, 0,
        HH, ISD, ISD, HH, 0, TT);
    sig_k<<<TT, 256>>>(x2, Wshg, sig);
    // 12) out = h + sum(slots) + shared*sigmoid
    final_k<<<(TT * HH) / 256, 256>>>(h, ys, shr, sig, out);
}